// round 1
// baseline (speedup 1.0000x reference)
#include <cuda_runtime.h>

#define NN 100000
#define IN_DIM 128
#define HID 32
#define ODIM 12

// Scratch (no allocation allowed; device globals are the sanctioned path)
__device__ __align__(128) float g_h1[NN * HID];    // feat @ W1
__device__ __align__(128) float g_agg1[NN * HID];  // edge-aggregated h1
__device__ __align__(128) float g_h2[NN * ODIM];   // layer-1 output @ W2
__device__ __align__(128) float g_deg[NN];         // in-degree (float)

__device__ __forceinline__ void red_add_v4(float* addr, float4 v) {
    asm volatile("red.global.add.v4.f32 [%0], {%1,%2,%3,%4};"
                 :: "l"(addr), "f"(v.x), "f"(v.y), "f"(v.z), "f"(v.w)
                 : "memory");
}

// ---------------------------------------------------------------------------
// Zero agg1, deg, and d_out in one pass.
__global__ void zero_kernel(float4* __restrict__ out4, int n_out4) {
    int i = blockIdx.x * blockDim.x + threadIdx.x;
    float4 z = make_float4(0.f, 0.f, 0.f, 0.f);
    const int n_a = (NN * HID) / 4;  // 800000
    const int n_d = NN / 4;          // 25000
    if (i < n_a) ((float4*)g_agg1)[i] = z;
    if (i < n_d) ((float4*)g_deg)[i] = z;
    if (i < n_out4) out4[i] = z;
}

// ---------------------------------------------------------------------------
// h1 = feat @ W1   [NN,128] x [128,32] -> [NN,32]
// Block: 256 thr = 8 warps; 64 rows/block (8 rows/warp), col = lane.
__global__ __launch_bounds__(256) void gemm1_kernel(const float4* __restrict__ feat4,
                                                    const float* __restrict__ W1) {
    __shared__ __align__(16) float fs[64][128];   // 32 KB
    __shared__ __align__(16) float Ws[128][32];   // 16 KB
    int tid = threadIdx.x;
    int base = blockIdx.x * 64;

    for (int i = tid; i < IN_DIM * HID; i += 256)
        ((float*)Ws)[i] = W1[i];

    float4* fs4 = (float4*)fs;
    for (int i = tid; i < 64 * 32; i += 256) {  // 64 rows x 32 float4
        int row = i >> 5, c = i & 31;
        int g = base + row;
        fs4[i] = (g < NN) ? feat4[(long long)g * 32 + c]
                          : make_float4(0.f, 0.f, 0.f, 0.f);
    }
    __syncthreads();

    int warp = tid >> 5, lane = tid & 31;
    int r0 = warp * 8;
    float acc[8];
#pragma unroll
    for (int r = 0; r < 8; r++) acc[r] = 0.f;

#pragma unroll 4
    for (int k = 0; k < IN_DIM; k += 4) {
        float w0 = Ws[k + 0][lane];
        float w1 = Ws[k + 1][lane];
        float w2 = Ws[k + 2][lane];
        float w3 = Ws[k + 3][lane];
#pragma unroll
        for (int r = 0; r < 8; r++) {
            float4 f = *(const float4*)&fs[r0 + r][k];
            acc[r] += f.x * w0 + f.y * w1 + f.z * w2 + f.w * w3;
        }
    }
#pragma unroll
    for (int r = 0; r < 8; r++) {
        int g = base + r0 + r;
        if (g < NN) g_h1[(long long)g * HID + lane] = acc[r];
    }
}

// ---------------------------------------------------------------------------
// Edge pass 1: gather h1[src] (128B row), red.v4 into agg1[dst]; count degree.
__global__ __launch_bounds__(256) void scatter1_kernel(const int* __restrict__ src,
                                                       const int* __restrict__ dst,
                                                       int E) {
    int e = blockIdx.x * blockDim.x + threadIdx.x;
    if (e >= E) return;
    int s = src[e];
    int d = dst[e];
    const float4* h = (const float4*)g_h1 + (long long)s * 8;
    float4 v[8];
#pragma unroll
    for (int j = 0; j < 8; j++) v[j] = h[j];
    float* a = g_agg1 + (long long)d * HID;
#pragma unroll
    for (int j = 0; j < 8; j++) red_add_v4(a + j * 4, v[j]);
    atomicAdd(&g_deg[d], 1.0f);
}

// ---------------------------------------------------------------------------
// x = relu(agg1/deg + b1)  (relu twice == once), then h2 = x @ W2  [32x12]
__global__ __launch_bounds__(256) void finalize1_kernel(const float* __restrict__ b1,
                                                        const float* __restrict__ W2) {
    __shared__ float W2s[HID * ODIM];
    __shared__ float b1s[HID];
    int tid = threadIdx.x;
    for (int i = tid; i < HID * ODIM; i += 256) W2s[i] = W2[i];
    if (tid < HID) b1s[tid] = b1[tid];
    __syncthreads();

    int n = blockIdx.x * blockDim.x + tid;
    if (n >= NN) return;

    float inv = 1.0f / fmaxf(g_deg[n], 1.0f);
    float acc[ODIM];
#pragma unroll
    for (int j = 0; j < ODIM; j++) acc[j] = 0.f;

    const float4* a4 = (const float4*)g_agg1 + (long long)n * 8;
#pragma unroll
    for (int c4 = 0; c4 < 8; c4++) {
        float4 av = a4[c4];
        int c = c4 * 4;
        float x0 = fmaxf(av.x * inv + b1s[c + 0], 0.f);
        float x1 = fmaxf(av.y * inv + b1s[c + 1], 0.f);
        float x2 = fmaxf(av.z * inv + b1s[c + 2], 0.f);
        float x3 = fmaxf(av.w * inv + b1s[c + 3], 0.f);
#pragma unroll
        for (int j = 0; j < ODIM; j++) {
            acc[j] += x0 * W2s[(c + 0) * ODIM + j]
                    + x1 * W2s[(c + 1) * ODIM + j]
                    + x2 * W2s[(c + 2) * ODIM + j]
                    + x3 * W2s[(c + 3) * ODIM + j];
        }
    }
    float4* o4 = (float4*)(g_h2 + (long long)n * ODIM);
    o4[0] = make_float4(acc[0], acc[1], acc[2], acc[3]);
    o4[1] = make_float4(acc[4], acc[5], acc[6], acc[7]);
    o4[2] = make_float4(acc[8], acc[9], acc[10], acc[11]);
}

// ---------------------------------------------------------------------------
// Edge pass 2: gather h2[src] (48B), red.v4 into out[dst].
__global__ __launch_bounds__(256) void scatter2_kernel(const int* __restrict__ src,
                                                       const int* __restrict__ dst,
                                                       float* __restrict__ out,
                                                       int E) {
    int e = blockIdx.x * blockDim.x + threadIdx.x;
    if (e >= E) return;
    int s = src[e];
    int d = dst[e];
    const float4* h = (const float4*)g_h2 + (long long)s * 3;
    float4 v0 = h[0], v1 = h[1], v2 = h[2];
    float* o = out + (long long)d * ODIM;
    red_add_v4(o + 0, v0);
    red_add_v4(o + 4, v1);
    red_add_v4(o + 8, v2);
}

// ---------------------------------------------------------------------------
// out = relu(out/deg + b2), in place
__global__ __launch_bounds__(256) void finalize2_kernel(float* __restrict__ out,
                                                        const float* __restrict__ b2) {
    __shared__ float b2s[ODIM];
    int tid = threadIdx.x;
    if (tid < ODIM) b2s[tid] = b2[tid];
    __syncthreads();

    int n = blockIdx.x * blockDim.x + tid;
    if (n >= NN) return;
    float inv = 1.0f / fmaxf(g_deg[n], 1.0f);
    float4* o4 = (float4*)(out + (long long)n * ODIM);
#pragma unroll
    for (int i = 0; i < 3; i++) {
        float4 v = o4[i];
        v.x = fmaxf(v.x * inv + b2s[i * 4 + 0], 0.f);
        v.y = fmaxf(v.y * inv + b2s[i * 4 + 1], 0.f);
        v.z = fmaxf(v.z * inv + b2s[i * 4 + 2], 0.f);
        v.w = fmaxf(v.w * inv + b2s[i * 4 + 3], 0.f);
        o4[i] = v;
    }
}

// ---------------------------------------------------------------------------
extern "C" void kernel_launch(void* const* d_in, const int* in_sizes, int n_in,
                              void* d_out, int out_size) {
    const float* feat = (const float*)d_in[0];  // [NN,128]
    const int*   src  = (const int*)d_in[1];    // [E]
    const int*   dst  = (const int*)d_in[2];    // [E]
    const float* W1   = (const float*)d_in[3];  // [128,32]
    const float* b1   = (const float*)d_in[4];  // [32]
    const float* W2   = (const float*)d_in[5];  // [32,12]
    const float* b2   = (const float*)d_in[6];  // [12]
    float* out = (float*)d_out;                 // [NN,12]

    int E = in_sizes[1];
    int n_out4 = out_size / 4;

    int zthreads = (NN * HID) / 4;  // largest zero range
    zero_kernel<<<(zthreads + 255) / 256, 256>>>((float4*)out, n_out4);
    gemm1_kernel<<<(NN + 63) / 64, 256>>>((const float4*)feat, W1);
    scatter1_kernel<<<(E + 255) / 256, 256>>>(src, dst, E);
    finalize1_kernel<<<(NN + 255) / 256, 256>>>(b1, W2);
    scatter2_kernel<<<(E + 255) / 256, 256>>>(src, dst, out, E);
    finalize2_kernel<<<(NN + 255) / 256, 256>>>(out, b2);
}

// round 2
// speedup vs baseline: 1.4707x; 1.4707x over previous
#include <cuda_runtime.h>

#define NN 100000
#define IN_DIM 128
#define HID 32
#define ODIM 12

// Scratch (no allocation allowed; device globals are the sanctioned path)
__device__ __align__(128) float g_h1[NN * HID];    // feat @ W1
__device__ __align__(128) float g_agg1[NN * HID];  // edge-aggregated h1
__device__ __align__(128) float g_h2[NN * ODIM];   // layer-1 output @ W2
__device__ __align__(128) float g_deg[NN];         // in-degree (float)

__device__ __forceinline__ void red_add_v4(float* addr, float4 v) {
    asm volatile("red.global.add.v4.f32 [%0], {%1,%2,%3,%4};"
                 :: "l"(addr), "f"(v.x), "f"(v.y), "f"(v.z), "f"(v.w)
                 : "memory");
}

// ---------------------------------------------------------------------------
// Zero agg1, deg, and d_out in one pass.
__global__ void zero_kernel(float4* __restrict__ out4, int n_out4) {
    int i = blockIdx.x * blockDim.x + threadIdx.x;
    float4 z = make_float4(0.f, 0.f, 0.f, 0.f);
    const int n_a = (NN * HID) / 4;  // 800000
    const int n_d = NN / 4;          // 25000
    if (i < n_a) ((float4*)g_agg1)[i] = z;
    if (i < n_d) ((float4*)g_deg)[i] = z;
    if (i < n_out4) out4[i] = z;
}

// ---------------------------------------------------------------------------
// h1 = feat @ W1   [NN,128] x [128,32] -> [NN,32]
// Block: 256 thr = 8 warps; 64 rows/block (8 rows/warp), col = lane.
__global__ __launch_bounds__(256) void gemm1_kernel(const float4* __restrict__ feat4,
                                                    const float* __restrict__ W1) {
    __shared__ __align__(16) float fs[64][128];   // 32 KB
    __shared__ __align__(16) float Ws[128][32];   // 16 KB
    int tid = threadIdx.x;
    int base = blockIdx.x * 64;

    for (int i = tid; i < IN_DIM * HID; i += 256)
        ((float*)Ws)[i] = W1[i];

    float4* fs4 = (float4*)fs;
    for (int i = tid; i < 64 * 32; i += 256) {  // 64 rows x 32 float4
        int row = i >> 5, c = i & 31;
        int g = base + row;
        fs4[i] = (g < NN) ? feat4[(long long)g * 32 + c]
                          : make_float4(0.f, 0.f, 0.f, 0.f);
    }
    __syncthreads();

    int warp = tid >> 5, lane = tid & 31;
    int r0 = warp * 8;
    float acc[8];
#pragma unroll
    for (int r = 0; r < 8; r++) acc[r] = 0.f;

#pragma unroll 4
    for (int k = 0; k < IN_DIM; k += 4) {
        float w0 = Ws[k + 0][lane];
        float w1 = Ws[k + 1][lane];
        float w2 = Ws[k + 2][lane];
        float w3 = Ws[k + 3][lane];
#pragma unroll
        for (int r = 0; r < 8; r++) {
            float4 f = *(const float4*)&fs[r0 + r][k];
            acc[r] += f.x * w0 + f.y * w1 + f.z * w2 + f.w * w3;
        }
    }
#pragma unroll
    for (int r = 0; r < 8; r++) {
        int g = base + r0 + r;
        if (g < NN) g_h1[(long long)g * HID + lane] = acc[r];
    }
}

// ---------------------------------------------------------------------------
// Edge pass 1, chunk-parallel: thread t -> edge t/8, float4-chunk t%8.
// Lanes 0-7 of a warp read consecutive 16B of the SAME h1 row -> coalesced
// (4 lines per warp LDG instead of 32), and the REDs are line-grouped too.
__global__ __launch_bounds__(256) void scatter1_kernel(const int* __restrict__ src,
                                                       const int* __restrict__ dst,
                                                       int E) {
    long long t = (long long)blockIdx.x * blockDim.x + threadIdx.x;
    int e = (int)(t >> 3);
    int c = (int)(t & 7);
    if (e >= E) return;
    int s = __ldg(&src[e]);
    int d = __ldg(&dst[e]);
    float4 v = ((const float4*)g_h1)[(long long)s * 8 + c];
    red_add_v4(g_agg1 + (long long)d * HID + c * 4, v);
    if (c == 0) atomicAdd(&g_deg[d], 1.0f);
}

// ---------------------------------------------------------------------------
// x = relu(agg1/deg + b1)  (relu twice == once), then h2 = x @ W2  [32x12]
__global__ __launch_bounds__(256) void finalize1_kernel(const float* __restrict__ b1,
                                                        const float* __restrict__ W2) {
    __shared__ float W2s[HID * ODIM];
    __shared__ float b1s[HID];
    int tid = threadIdx.x;
    for (int i = tid; i < HID * ODIM; i += 256) W2s[i] = W2[i];
    if (tid < HID) b1s[tid] = b1[tid];
    __syncthreads();

    int n = blockIdx.x * blockDim.x + tid;
    if (n >= NN) return;

    float inv = 1.0f / fmaxf(g_deg[n], 1.0f);
    float acc[ODIM];
#pragma unroll
    for (int j = 0; j < ODIM; j++) acc[j] = 0.f;

    const float4* a4 = (const float4*)g_agg1 + (long long)n * 8;
#pragma unroll
    for (int c4 = 0; c4 < 8; c4++) {
        float4 av = a4[c4];
        int c = c4 * 4;
        float x0 = fmaxf(av.x * inv + b1s[c + 0], 0.f);
        float x1 = fmaxf(av.y * inv + b1s[c + 1], 0.f);
        float x2 = fmaxf(av.z * inv + b1s[c + 2], 0.f);
        float x3 = fmaxf(av.w * inv + b1s[c + 3], 0.f);
#pragma unroll
        for (int j = 0; j < ODIM; j++) {
            acc[j] += x0 * W2s[(c + 0) * ODIM + j]
                    + x1 * W2s[(c + 1) * ODIM + j]
                    + x2 * W2s[(c + 2) * ODIM + j]
                    + x3 * W2s[(c + 3) * ODIM + j];
        }
    }
    float4* o4 = (float4*)(g_h2 + (long long)n * ODIM);
    o4[0] = make_float4(acc[0], acc[1], acc[2], acc[3]);
    o4[1] = make_float4(acc[4], acc[5], acc[6], acc[7]);
    o4[2] = make_float4(acc[8], acc[9], acc[10], acc[11]);
}

// ---------------------------------------------------------------------------
// Edge pass 2, chunk-parallel: thread t -> edge t/3, float4-chunk t%3.
__global__ __launch_bounds__(256) void scatter2_kernel(const int* __restrict__ src,
                                                       const int* __restrict__ dst,
                                                       float* __restrict__ out,
                                                       int E) {
    long long t = (long long)blockIdx.x * blockDim.x + threadIdx.x;
    int e = (int)(t / 3);
    int c = (int)(t - (long long)e * 3);
    if (e >= E) return;
    int s = __ldg(&src[e]);
    int d = __ldg(&dst[e]);
    float4 v = ((const float4*)g_h2)[(long long)s * 3 + c];
    red_add_v4(out + (long long)d * ODIM + c * 4, v);
}

// ---------------------------------------------------------------------------
// out = relu(out/deg + b2), in place
__global__ __launch_bounds__(256) void finalize2_kernel(float* __restrict__ out,
                                                        const float* __restrict__ b2) {
    __shared__ float b2s[ODIM];
    int tid = threadIdx.x;
    if (tid < ODIM) b2s[tid] = b2[tid];
    __syncthreads();

    int n = blockIdx.x * blockDim.x + tid;
    if (n >= NN) return;
    float inv = 1.0f / fmaxf(g_deg[n], 1.0f);
    float4* o4 = (float4*)(out + (long long)n * ODIM);
#pragma unroll
    for (int i = 0; i < 3; i++) {
        float4 v = o4[i];
        v.x = fmaxf(v.x * inv + b2s[i * 4 + 0], 0.f);
        v.y = fmaxf(v.y * inv + b2s[i * 4 + 1], 0.f);
        v.z = fmaxf(v.z * inv + b2s[i * 4 + 2], 0.f);
        v.w = fmaxf(v.w * inv + b2s[i * 4 + 3], 0.f);
        o4[i] = v;
    }
}

// ---------------------------------------------------------------------------
extern "C" void kernel_launch(void* const* d_in, const int* in_sizes, int n_in,
                              void* d_out, int out_size) {
    const float* feat = (const float*)d_in[0];  // [NN,128]
    const int*   src  = (const int*)d_in[1];    // [E]
    const int*   dst  = (const int*)d_in[2];    // [E]
    const float* W1   = (const float*)d_in[3];  // [128,32]
    const float* b1   = (const float*)d_in[4];  // [32]
    const float* W2   = (const float*)d_in[5];  // [32,12]
    const float* b2   = (const float*)d_in[6];  // [12]
    float* out = (float*)d_out;                 // [NN,12]

    int E = in_sizes[1];
    int n_out4 = out_size / 4;

    int zthreads = (NN * HID) / 4;  // largest zero range
    zero_kernel<<<(zthreads + 255) / 256, 256>>>((float4*)out, n_out4);
    gemm1_kernel<<<(NN + 63) / 64, 256>>>((const float4*)feat, W1);
    {
        long long t1 = (long long)E * 8;
        scatter1_kernel<<<(int)((t1 + 255) / 256), 256>>>(src, dst, E);
    }
    finalize1_kernel<<<(NN + 255) / 256, 256>>>(b1, W2);
    {
        long long t2 = (long long)E * 3;
        scatter2_kernel<<<(int)((t2 + 255) / 256), 256>>>(src, dst, out, E);
    }
    finalize2_kernel<<<(NN + 255) / 256, 256>>>(out, b2);
}